// round 2
// baseline (speedup 1.0000x reference)
#include <cuda_runtime.h>
#include <cstdint>

// LTC scan, round 2: register-resident W_r + packed f32x2 FMA.
// R1 post-mortem: shared crossbar bound (L1=77%) from per-thread-unique W LDS.
// Fix: each lane-pair (jj, half) owns hidden unit jj with k split in halves of 64;
// W_r half-row lives in 64 registers as f32x2 pairs, h/x read from shared as
// broadcast ld.shared.v2.b64 (16B -> two b64 f32x2 regs, no repack MOVs).
// fma.rn.f32x2 halves FMA instruction count (SASS FFMA2, PTX-only pattern).

#define Bsz 512
#define Ssz 512
#define Dsz 128
#define Hsz 128
#define PAD 132          // W_in row stride: 528B, 16B aligned, conflict-free
#define THREADS 256
#define ROWS 4
#define UNFOLDS 6

__device__ __forceinline__ unsigned long long ffma2(unsigned long long a,
                                                    unsigned long long b,
                                                    unsigned long long c) {
    unsigned long long d;
    asm("fma.rn.f32x2 %0, %1, %2, %3;" : "=l"(d) : "l"(a), "l"(b), "l"(c));
    return d;
}

__device__ __forceinline__ float f2sum(unsigned long long v) {
    float lo, hi;
    asm("mov.b64 {%0, %1}, %2;" : "=f"(lo), "=f"(hi) : "l"(v));
    return lo + hi;
}

__device__ __forceinline__ float ftanh(float s) {
    float e = __expf(2.0f * s);
    return 1.0f - __fdividef(2.0f, e + 1.0f);
}

__global__ void __launch_bounds__(THREADS, 1)
ltc_kernel(const float* __restrict__ x,
           const float* __restrict__ W_in,
           const float* __restrict__ b_in,
           const float* __restrict__ W_r,
           const float* __restrict__ b_r,
           const float* __restrict__ W_fc,
           const float* __restrict__ b_fc,
           float* __restrict__ out)
{
    extern __shared__ float sm[];
    float* Win_s = sm;                      // [Hsz][PAD]
    float* h_s   = Win_s + Hsz * PAD;       // [2][ROWS][Hsz] double-buffered
    float* x_s   = h_s + 2 * ROWS * Hsz;    // [ROWS][Dsz] (reused as reduce scratch)

    const int tid = threadIdx.x;

    // Stage W_in into shared (one-time).
    for (int i = tid; i < Hsz * Dsz; i += THREADS) {
        int j = i >> 7, k = i & 127;
        Win_s[j * PAD + k] = W_in[i];
    }

    const int jj   = tid >> 1;      // hidden unit owned (0..127)
    const int half = tid & 1;       // k-half (lane pairs 2m, 2m+1)
    const int k0   = half << 6;     // 0 or 64
    const int base = blockIdx.x * ROWS;

    // Register-resident W_r half-row as 32 packed f32x2 (one-time GMEM load).
    unsigned long long wr[32];
    {
        const ulonglong2* wp = (const ulonglong2*)(W_r + jj * Hsz + k0);
        #pragma unroll
        for (int c = 0; c < 16; ++c) {
            ulonglong2 v = wp[c];
            wr[2 * c]     = v.x;
            wr[2 * c + 1] = v.y;
        }
    }

    const float bi  = b_in[jj];
    const float bb  = b_r[jj];
    const float wfc = W_fc[jj];

    float h0 = 0.f, h1 = 0.f, h2 = 0.f, h3 = 0.f;

    // x staging: each thread owns 2 elements of the CTA's [ROWS][Dsz] slab.
    const int e0r = tid >> 7,             e0k = tid & 127;
    const int e1r = (tid + THREADS) >> 7, e1k = (tid + THREADS) & 127;
    const size_t g0 = (size_t)(base + e0r) * Ssz * Dsz + e0k;
    const size_t g1 = (size_t)(base + e1r) * Ssz * Dsz + e1k;

    float xa = x[g0];
    float xb = x[g1];

    for (int t = 0; t < Ssz; ++t) {
        x_s[e0r * Dsz + e0k] = xa;
        x_s[e1r * Dsz + e1k] = xb;
        __syncthreads();   // orders x stores (and one-time W_in fill) before reads

        if (t + 1 < Ssz) {
            xa = x[g0 + (size_t)(t + 1) * Dsz];
            xb = x[g1 + (size_t)(t + 1) * Dsz];
        }

        // xin = W_in @ x + b_in  (W_in from shared, x broadcast, packed FMA)
        unsigned long long a0 = 0ull, a1 = 0ull, a2 = 0ull, a3 = 0ull;
        unsigned long long a4 = 0ull, a5 = 0ull, a6 = 0ull, a7 = 0ull;
        const float* wirow = Win_s + jj * PAD + k0;
        #pragma unroll
        for (int c = 0; c < 16; ++c) {
            ulonglong2 wv = *(const ulonglong2*)(wirow + 4 * c);
            ulonglong2 v0 = *(const ulonglong2*)(x_s + 0 * Dsz + k0 + 4 * c);
            ulonglong2 v1 = *(const ulonglong2*)(x_s + 1 * Dsz + k0 + 4 * c);
            ulonglong2 v2 = *(const ulonglong2*)(x_s + 2 * Dsz + k0 + 4 * c);
            ulonglong2 v3 = *(const ulonglong2*)(x_s + 3 * Dsz + k0 + 4 * c);
            a0 = ffma2(wv.x, v0.x, a0);  a1 = ffma2(wv.y, v0.y, a1);
            a2 = ffma2(wv.x, v1.x, a2);  a3 = ffma2(wv.y, v1.y, a3);
            a4 = ffma2(wv.x, v2.x, a4);  a5 = ffma2(wv.y, v2.y, a5);
            a6 = ffma2(wv.x, v3.x, a6);  a7 = ffma2(wv.y, v3.y, a7);
        }
        float xin0 = f2sum(a0) + f2sum(a1);
        float xin1 = f2sum(a2) + f2sum(a3);
        float xin2 = f2sum(a4) + f2sum(a5);
        float xin3 = f2sum(a6) + f2sum(a7);
        xin0 += __shfl_xor_sync(0xffffffffu, xin0, 1);
        xin1 += __shfl_xor_sync(0xffffffffu, xin1, 1);
        xin2 += __shfl_xor_sync(0xffffffffu, xin2, 1);
        xin3 += __shfl_xor_sync(0xffffffffu, xin3, 1);
        xin0 += bi; xin1 += bi; xin2 += bi; xin3 += bi;

        // 6 ODE unfolds: h = 0.9h + 0.1*tanh(xin + h@W_r^T + b_r)
        #pragma unroll 1
        for (int u = 0; u < UNFOLDS; ++u) {
            float* hb = h_s + (u & 1) * (ROWS * Hsz);
            // Both halves hold identical h (shfl-combined); split the stores.
            if (half == 0) {
                hb[0 * Hsz + jj] = h0;
                hb[1 * Hsz + jj] = h1;
            } else {
                hb[2 * Hsz + jj] = h2;
                hb[3 * Hsz + jj] = h3;
            }
            __syncthreads();

            unsigned long long c0 = 0ull, c1 = 0ull, c2 = 0ull, c3 = 0ull;
            unsigned long long c4 = 0ull, c5 = 0ull, c6 = 0ull, c7 = 0ull;
            #pragma unroll
            for (int c = 0; c < 16; ++c) {
                ulonglong2 v0 = *(const ulonglong2*)(hb + 0 * Hsz + k0 + 4 * c);
                ulonglong2 v1 = *(const ulonglong2*)(hb + 1 * Hsz + k0 + 4 * c);
                ulonglong2 v2 = *(const ulonglong2*)(hb + 2 * Hsz + k0 + 4 * c);
                ulonglong2 v3 = *(const ulonglong2*)(hb + 3 * Hsz + k0 + 4 * c);
                c0 = ffma2(wr[2 * c], v0.x, c0);  c1 = ffma2(wr[2 * c + 1], v0.y, c1);
                c2 = ffma2(wr[2 * c], v1.x, c2);  c3 = ffma2(wr[2 * c + 1], v1.y, c3);
                c4 = ffma2(wr[2 * c], v2.x, c4);  c5 = ffma2(wr[2 * c + 1], v2.y, c5);
                c6 = ffma2(wr[2 * c], v3.x, c6);  c7 = ffma2(wr[2 * c + 1], v3.y, c7);
            }
            float s0 = f2sum(c0) + f2sum(c1);
            float s1 = f2sum(c2) + f2sum(c3);
            float s2 = f2sum(c4) + f2sum(c5);
            float s3 = f2sum(c6) + f2sum(c7);
            s0 += __shfl_xor_sync(0xffffffffu, s0, 1);
            s1 += __shfl_xor_sync(0xffffffffu, s1, 1);
            s2 += __shfl_xor_sync(0xffffffffu, s2, 1);
            s3 += __shfl_xor_sync(0xffffffffu, s3, 1);
            h0 = 0.9f * h0 + 0.1f * ftanh(xin0 + bb + s0);
            h1 = 0.9f * h1 + 0.1f * ftanh(xin1 + bb + s1);
            h2 = 0.9f * h2 + 0.1f * ftanh(xin2 + bb + s2);
            h3 = 0.9f * h3 + 0.1f * ftanh(xin3 + bb + s3);
        }
    }

    // Final projection: out[b] = b_fc + sum_j h[b][j] * W_fc[j]
    __syncthreads();
    float* red = x_s;   // [ROWS][Hsz] scratch
    if (half == 0) {
        red[0 * Hsz + jj] = h0 * wfc;
        red[1 * Hsz + jj] = h1 * wfc;
    } else {
        red[2 * Hsz + jj] = h2 * wfc;
        red[3 * Hsz + jj] = h3 * wfc;
    }
    __syncthreads();
    if (tid < ROWS) {
        float s = b_fc[0];
        const float* rr = red + tid * Hsz;
        #pragma unroll
        for (int k = 0; k < Hsz; ++k) s += rr[k];
        out[base + tid] = s;
    }
}

extern "C" void kernel_launch(void* const* d_in, const int* in_sizes, int n_in,
                              void* d_out, int out_size)
{
    const float* x    = (const float*)d_in[0];
    const float* W_in = (const float*)d_in[1];
    const float* b_in = (const float*)d_in[2];
    const float* W_r  = (const float*)d_in[3];
    const float* b_r  = (const float*)d_in[4];
    const float* W_fc = (const float*)d_in[5];
    const float* b_fc = (const float*)d_in[6];
    float* out = (float*)d_out;

    const size_t smem = (size_t)(Hsz * PAD + 2 * ROWS * Hsz + ROWS * Dsz) * sizeof(float);
    cudaFuncSetAttribute(ltc_kernel, cudaFuncAttributeMaxDynamicSharedMemorySize, (int)smem);

    ltc_kernel<<<Bsz / ROWS, THREADS, smem>>>(x, W_in, b_in, W_r, b_r, W_fc, b_fc, out);
}

// round 3
// speedup vs baseline: 1.9327x; 1.9327x over previous
#include <cuda_runtime.h>
#include <cstdint>

// LTC scan, round 3.
// R2 post-mortem: still L1TEX-bound; even/odd-lane k-split made h loads 2-line
// (2 wavefronts) and added shfl+f2sum to the serial chain.
// R3: thread owns one FULL hidden unit j (W_r row j = 128 regs = 64 b64 f32x2
// pairs); every h read is a pure all-lane 16B broadcast LDS.128 (1 wavefront);
// dot product completes in-thread (no shuffles). Input projection hoisted to a
// separate parallel GEMM into __device__ scratch, removing W_in traffic and
// its FMAs from the sequential scan.

#define Bsz 512
#define Ssz 512
#define Dsz 128
#define Hsz 128
#define ROWS 4
#define UNFOLDS 6

__device__ float g_xin[(size_t)Bsz * Ssz * Hsz];   // [b][s][h], 128 MiB scratch

__device__ __forceinline__ unsigned long long ffma2(unsigned long long a,
                                                    unsigned long long b,
                                                    unsigned long long c) {
    unsigned long long d;
    asm("fma.rn.f32x2 %0, %1, %2, %3;" : "=l"(d) : "l"(a), "l"(b), "l"(c));
    return d;
}

__device__ __forceinline__ float f2sum(unsigned long long v) {
    float lo, hi;
    asm("mov.b64 {%0, %1}, %2;" : "=f"(lo), "=f"(hi) : "l"(v));
    return lo + hi;
}

__device__ __forceinline__ float ftanh(float s) {
    float e = __expf(2.0f * s);
    return 1.0f - __fdividef(2.0f, e + 1.0f);
}

// ---------------------------------------------------------------------------
// Kernel 1: xin[b,s,j] = sum_d x[b,s,d] * W_in[j,d] + b_in[j]
// Thread = j, W_in row in registers, x rows broadcast from shared.
// grid 2048 x 128 threads; each CTA does 128 (b,s)-rows in chunks of 4.
// ---------------------------------------------------------------------------
__global__ void __launch_bounds__(128, 3)
xin_kernel(const float* __restrict__ x,
           const float* __restrict__ W_in,
           const float* __restrict__ b_in)
{
    __shared__ float xs[2][ROWS * Dsz];

    const int j = threadIdx.x;

    unsigned long long wi[64];
    {
        const ulonglong2* wp = (const ulonglong2*)(W_in + j * Dsz);
        #pragma unroll
        for (int c = 0; c < 32; ++c) {
            ulonglong2 v = wp[c];
            wi[2 * c]     = v.x;
            wi[2 * c + 1] = v.y;
        }
    }
    const float bi = b_in[j];

    const int m0 = blockIdx.x * 128;

    float xf[ROWS];
    #pragma unroll
    for (int r = 0; r < ROWS; ++r)
        xf[r] = x[(size_t)(m0 + r) * Dsz + j];

    #pragma unroll 1
    for (int ch = 0; ch < 32; ++ch) {
        float* xb = xs[ch & 1];
        #pragma unroll
        for (int r = 0; r < ROWS; ++r)
            xb[r * Dsz + j] = xf[r];
        __syncthreads();

        if (ch < 31) {
            #pragma unroll
            for (int r = 0; r < ROWS; ++r)
                xf[r] = x[(size_t)(m0 + (ch + 1) * ROWS + r) * Dsz + j];
        }

        unsigned long long a0 = 0ull, a1 = 0ull, a2 = 0ull, a3 = 0ull;
        unsigned long long a4 = 0ull, a5 = 0ull, a6 = 0ull, a7 = 0ull;
        #pragma unroll
        for (int c = 0; c < 32; ++c) {
            ulonglong2 v0 = *(const ulonglong2*)(xb + 0 * Dsz + 4 * c);
            ulonglong2 v1 = *(const ulonglong2*)(xb + 1 * Dsz + 4 * c);
            ulonglong2 v2 = *(const ulonglong2*)(xb + 2 * Dsz + 4 * c);
            ulonglong2 v3 = *(const ulonglong2*)(xb + 3 * Dsz + 4 * c);
            a0 = ffma2(wi[2 * c], v0.x, a0);  a1 = ffma2(wi[2 * c + 1], v0.y, a1);
            a2 = ffma2(wi[2 * c], v1.x, a2);  a3 = ffma2(wi[2 * c + 1], v1.y, a3);
            a4 = ffma2(wi[2 * c], v2.x, a4);  a5 = ffma2(wi[2 * c + 1], v2.y, a5);
            a6 = ffma2(wi[2 * c], v3.x, a6);  a7 = ffma2(wi[2 * c + 1], v3.y, a7);
        }
        const int m = m0 + ch * ROWS;
        g_xin[(size_t)(m + 0) * Hsz + j] = f2sum(a0) + f2sum(a1) + bi;
        g_xin[(size_t)(m + 1) * Hsz + j] = f2sum(a2) + f2sum(a3) + bi;
        g_xin[(size_t)(m + 2) * Hsz + j] = f2sum(a4) + f2sum(a5) + bi;
        g_xin[(size_t)(m + 3) * Hsz + j] = f2sum(a6) + f2sum(a7) + bi;
        // double buffer -> one barrier per chunk is sufficient
    }
}

// ---------------------------------------------------------------------------
// Kernel 2: the sequential scan. grid 128 x 128 threads, 4 rows/CTA.
// ---------------------------------------------------------------------------
__global__ void __launch_bounds__(128, 1)
ltc_main(const float* __restrict__ W_r,
         const float* __restrict__ b_r,
         const float* __restrict__ W_fc,
         const float* __restrict__ b_fc,
         float* __restrict__ out)
{
    __shared__ float hs[2][ROWS][Hsz];
    __shared__ float red[ROWS][Hsz];

    const int j    = threadIdx.x;
    const int base = blockIdx.x * ROWS;

    unsigned long long wr[64];
    {
        const ulonglong2* wp = (const ulonglong2*)(W_r + j * Hsz);
        #pragma unroll
        for (int c = 0; c < 32; ++c) {
            ulonglong2 v = wp[c];
            wr[2 * c]     = v.x;
            wr[2 * c + 1] = v.y;
        }
    }
    const float bb  = b_r[j];
    const float wfc = W_fc[j];

    float h0 = 0.f, h1 = 0.f, h2 = 0.f, h3 = 0.f;

    const size_t xs0 = (size_t)(base + 0) * Ssz * Hsz + j;
    const size_t xs1 = (size_t)(base + 1) * Ssz * Hsz + j;
    const size_t xs2 = (size_t)(base + 2) * Ssz * Hsz + j;
    const size_t xs3 = (size_t)(base + 3) * Ssz * Hsz + j;

    float xf0 = g_xin[xs0], xf1 = g_xin[xs1], xf2 = g_xin[xs2], xf3 = g_xin[xs3];

    #pragma unroll 1
    for (int t = 0; t < Ssz; ++t) {
        const float xin0 = xf0 + bb, xin1 = xf1 + bb, xin2 = xf2 + bb, xin3 = xf3 + bb;
        if (t + 1 < Ssz) {
            const size_t o = (size_t)(t + 1) * Hsz;
            xf0 = g_xin[xs0 + o];
            xf1 = g_xin[xs1 + o];
            xf2 = g_xin[xs2 + o];
            xf3 = g_xin[xs3 + o];
        }

        #pragma unroll 1
        for (int u = 0; u < UNFOLDS; ++u) {
            float (*hb)[Hsz] = hs[u & 1];
            hb[0][j] = h0;
            hb[1][j] = h1;
            hb[2][j] = h2;
            hb[3][j] = h3;
            __syncthreads();   // double-buffered: one barrier per unfold

            unsigned long long a0 = 0ull, a1 = 0ull, a2 = 0ull, a3 = 0ull;
            unsigned long long a4 = 0ull, a5 = 0ull, a6 = 0ull, a7 = 0ull;
            #pragma unroll          // full unroll required: wr[] is a register array
            for (int c = 0; c < 32; ++c) {
                ulonglong2 v0 = *(const ulonglong2*)&hb[0][4 * c];  // all-lane broadcast
                ulonglong2 v1 = *(const ulonglong2*)&hb[1][4 * c];
                ulonglong2 v2 = *(const ulonglong2*)&hb[2][4 * c];
                ulonglong2 v3 = *(const ulonglong2*)&hb[3][4 * c];
                a0 = ffma2(wr[2 * c], v0.x, a0);  a1 = ffma2(wr[2 * c + 1], v0.y, a1);
                a2 = ffma2(wr[2 * c], v1.x, a2);  a3 = ffma2(wr[2 * c + 1], v1.y, a3);
                a4 = ffma2(wr[2 * c], v2.x, a4);  a5 = ffma2(wr[2 * c + 1], v2.y, a5);
                a6 = ffma2(wr[2 * c], v3.x, a6);  a7 = ffma2(wr[2 * c + 1], v3.y, a7);
            }
            h0 = 0.9f * h0 + 0.1f * ftanh(xin0 + f2sum(a0) + f2sum(a1));
            h1 = 0.9f * h1 + 0.1f * ftanh(xin1 + f2sum(a2) + f2sum(a3));
            h2 = 0.9f * h2 + 0.1f * ftanh(xin2 + f2sum(a4) + f2sum(a5));
            h3 = 0.9f * h3 + 0.1f * ftanh(xin3 + f2sum(a6) + f2sum(a7));
        }
    }

    // out[b] = b_fc + sum_j h[b][j] * W_fc[j]
    __syncthreads();
    red[0][j] = h0 * wfc;
    red[1][j] = h1 * wfc;
    red[2][j] = h2 * wfc;
    red[3][j] = h3 * wfc;
    __syncthreads();

    const int wid = j >> 5, lane = j & 31;
    float4 v = *(const float4*)&red[wid][4 * lane];
    float s = (v.x + v.y) + (v.z + v.w);
    #pragma unroll
    for (int d = 16; d > 0; d >>= 1)
        s += __shfl_xor_sync(0xffffffffu, s, d);
    if (lane == 0)
        out[base + wid] = s + b_fc[0];
}

extern "C" void kernel_launch(void* const* d_in, const int* in_sizes, int n_in,
                              void* d_out, int out_size)
{
    const float* x    = (const float*)d_in[0];
    const float* W_in = (const float*)d_in[1];
    const float* b_in = (const float*)d_in[2];
    const float* W_r  = (const float*)d_in[3];
    const float* b_r  = (const float*)d_in[4];
    const float* W_fc = (const float*)d_in[5];
    const float* b_fc = (const float*)d_in[6];
    float* out = (float*)d_out;

    xin_kernel<<<(Bsz * Ssz) / 128, 128>>>(x, W_in, b_in);
    ltc_main<<<Bsz / ROWS, 128>>>(W_r, b_r, W_fc, b_fc, out);
}

// round 4
// speedup vs baseline: 2.0630x; 1.0674x over previous
#include <cuda_runtime.h>
#include <cstdint>

// LTC scan, round 4.
// R3 post-mortem: scan latency-bound (occ 6.3% = 1 warp/SMSP, issue 36%,
// fma pipe only 37% busy). Fix: ROWS 4->2, grid 256, 2 CTAs/SM co-resident
// (2 warps per SMSP) so each CTA's LDS/tanh/barrier stalls are hidden by the
// sibling CTA. Dataflow unchanged: W_r row j in 128 registers per thread,
// h broadcast via conflict-free LDS.128, dot product completes in-thread.

#define Bsz 512
#define Ssz 512
#define Dsz 128
#define Hsz 128
#define ROWS 2
#define UNFOLDS 6

__device__ float g_xin[(size_t)Bsz * Ssz * Hsz];   // [b][s][h] scratch

__device__ __forceinline__ unsigned long long ffma2(unsigned long long a,
                                                    unsigned long long b,
                                                    unsigned long long c) {
    unsigned long long d;
    asm("fma.rn.f32x2 %0, %1, %2, %3;" : "=l"(d) : "l"(a), "l"(b), "l"(c));
    return d;
}

__device__ __forceinline__ float f2sum(unsigned long long v) {
    float lo, hi;
    asm("mov.b64 {%0, %1}, %2;" : "=f"(lo), "=f"(hi) : "l"(v));
    return lo + hi;
}

__device__ __forceinline__ float ftanh(float s) {
    float e = __expf(2.0f * s);
    return 1.0f - __fdividef(2.0f, e + 1.0f);
}

// ---------------------------------------------------------------------------
// Kernel 1: xin[b,s,j] = sum_d x[b,s,d] * W_in[j,d] + b_in[j]
// ---------------------------------------------------------------------------
__global__ void __launch_bounds__(128, 3)
xin_kernel(const float* __restrict__ x,
           const float* __restrict__ W_in,
           const float* __restrict__ b_in)
{
    __shared__ float xs[2][4 * Dsz];

    const int j = threadIdx.x;

    unsigned long long wi[64];
    {
        const ulonglong2* wp = (const ulonglong2*)(W_in + j * Dsz);
        #pragma unroll
        for (int c = 0; c < 32; ++c) {
            ulonglong2 v = wp[c];
            wi[2 * c]     = v.x;
            wi[2 * c + 1] = v.y;
        }
    }
    const float bi = b_in[j];

    const int m0 = blockIdx.x * 128;

    float xf[4];
    #pragma unroll
    for (int r = 0; r < 4; ++r)
        xf[r] = x[(size_t)(m0 + r) * Dsz + j];

    #pragma unroll 1
    for (int ch = 0; ch < 32; ++ch) {
        float* xb = xs[ch & 1];
        #pragma unroll
        for (int r = 0; r < 4; ++r)
            xb[r * Dsz + j] = xf[r];
        __syncthreads();

        if (ch < 31) {
            #pragma unroll
            for (int r = 0; r < 4; ++r)
                xf[r] = x[(size_t)(m0 + (ch + 1) * 4 + r) * Dsz + j];
        }

        unsigned long long a0 = 0ull, a1 = 0ull, a2 = 0ull, a3 = 0ull;
        unsigned long long a4 = 0ull, a5 = 0ull, a6 = 0ull, a7 = 0ull;
        #pragma unroll
        for (int c = 0; c < 32; ++c) {
            ulonglong2 v0 = *(const ulonglong2*)(xb + 0 * Dsz + 4 * c);
            ulonglong2 v1 = *(const ulonglong2*)(xb + 1 * Dsz + 4 * c);
            ulonglong2 v2 = *(const ulonglong2*)(xb + 2 * Dsz + 4 * c);
            ulonglong2 v3 = *(const ulonglong2*)(xb + 3 * Dsz + 4 * c);
            a0 = ffma2(wi[2 * c], v0.x, a0);  a1 = ffma2(wi[2 * c + 1], v0.y, a1);
            a2 = ffma2(wi[2 * c], v1.x, a2);  a3 = ffma2(wi[2 * c + 1], v1.y, a3);
            a4 = ffma2(wi[2 * c], v2.x, a4);  a5 = ffma2(wi[2 * c + 1], v2.y, a5);
            a6 = ffma2(wi[2 * c], v3.x, a6);  a7 = ffma2(wi[2 * c + 1], v3.y, a7);
        }
        const int m = m0 + ch * 4;
        g_xin[(size_t)(m + 0) * Hsz + j] = f2sum(a0) + f2sum(a1) + bi;
        g_xin[(size_t)(m + 1) * Hsz + j] = f2sum(a2) + f2sum(a3) + bi;
        g_xin[(size_t)(m + 2) * Hsz + j] = f2sum(a4) + f2sum(a5) + bi;
        g_xin[(size_t)(m + 3) * Hsz + j] = f2sum(a6) + f2sum(a7) + bi;
    }
}

// ---------------------------------------------------------------------------
// Kernel 2: sequential scan. grid 256 x 128 threads, 2 rows/CTA,
// 2 CTAs co-resident per SM for latency hiding.
// ---------------------------------------------------------------------------
__global__ void __launch_bounds__(128, 2)
ltc_main(const float* __restrict__ W_r,
         const float* __restrict__ b_r,
         const float* __restrict__ W_fc,
         const float* __restrict__ b_fc,
         float* __restrict__ out)
{
    __shared__ float hs[2][ROWS][Hsz];
    __shared__ float red[ROWS][Hsz];

    const int j    = threadIdx.x;
    const int base = blockIdx.x * ROWS;

    unsigned long long wr[64];
    {
        const ulonglong2* wp = (const ulonglong2*)(W_r + j * Hsz);
        #pragma unroll
        for (int c = 0; c < 32; ++c) {
            ulonglong2 v = wp[c];
            wr[2 * c]     = v.x;
            wr[2 * c + 1] = v.y;
        }
    }
    const float bb  = b_r[j];
    const float wfc = W_fc[j];

    float h0 = 0.f, h1 = 0.f;

    const size_t xs0 = (size_t)(base + 0) * Ssz * Hsz + j;
    const size_t xs1 = (size_t)(base + 1) * Ssz * Hsz + j;

    float xf0 = g_xin[xs0], xf1 = g_xin[xs1];

    #pragma unroll 1
    for (int t = 0; t < Ssz; ++t) {
        const float xin0 = xf0 + bb, xin1 = xf1 + bb;
        if (t + 1 < Ssz) {
            const size_t o = (size_t)(t + 1) * Hsz;
            xf0 = g_xin[xs0 + o];
            xf1 = g_xin[xs1 + o];
        }

        #pragma unroll 1
        for (int u = 0; u < UNFOLDS; ++u) {
            float (*hb)[Hsz] = hs[u & 1];
            hb[0][j] = h0;
            hb[1][j] = h1;
            __syncthreads();   // double-buffered: one barrier per unfold

            unsigned long long a0 = 0ull, a1 = 0ull, a2 = 0ull, a3 = 0ull;
            #pragma unroll          // full unroll: wr[] must stay in registers
            for (int c = 0; c < 32; ++c) {
                ulonglong2 v0 = *(const ulonglong2*)&hb[0][4 * c];  // broadcast
                ulonglong2 v1 = *(const ulonglong2*)&hb[1][4 * c];
                a0 = ffma2(wr[2 * c], v0.x, a0);  a1 = ffma2(wr[2 * c + 1], v0.y, a1);
                a2 = ffma2(wr[2 * c], v1.x, a2);  a3 = ffma2(wr[2 * c + 1], v1.y, a3);
            }
            h0 = 0.9f * h0 + 0.1f * ftanh(xin0 + f2sum(a0) + f2sum(a1));
            h1 = 0.9f * h1 + 0.1f * ftanh(xin1 + f2sum(a2) + f2sum(a3));
        }
    }

    // out[b] = b_fc + sum_j h[b][j] * W_fc[j]
    __syncthreads();
    red[0][j] = h0 * wfc;
    red[1][j] = h1 * wfc;
    __syncthreads();

    const int wid = j >> 5, lane = j & 31;
    if (wid < ROWS) {
        float4 v = *(const float4*)&red[wid][4 * lane];
        float s = (v.x + v.y) + (v.z + v.w);
        #pragma unroll
        for (int d = 16; d > 0; d >>= 1)
            s += __shfl_xor_sync(0xffffffffu, s, d);
        if (lane == 0)
            out[base + wid] = s + b_fc[0];
    }
}

extern "C" void kernel_launch(void* const* d_in, const int* in_sizes, int n_in,
                              void* d_out, int out_size)
{
    const float* x    = (const float*)d_in[0];
    const float* W_in = (const float*)d_in[1];
    const float* b_in = (const float*)d_in[2];
    const float* W_r  = (const float*)d_in[3];
    const float* b_r  = (const float*)d_in[4];
    const float* W_fc = (const float*)d_in[5];
    const float* b_fc = (const float*)d_in[6];
    float* out = (float*)d_out;

    xin_kernel<<<(Bsz * Ssz) / 128, 128>>>(x, W_in, b_in);
    ltc_main<<<Bsz / ROWS, 128>>>(W_r, b_r, W_fc, b_fc, out);
}

// round 5
// speedup vs baseline: 2.3473x; 1.1378x over previous
#include <cuda_runtime.h>
#include <cstdint>

// LTC scan, round 5.
// R4 post-mortem: L1TEX 74% = binder; each 16B h-load fed only 2 FFMA2.
// R5: 256 thr/CTA, 4 rows/CTA, grid 128. Thread owns a j-PAIR (2 hidden units)
// over a k-HALF (64 cols) for a row-pair -> each broadcast h-load feeds 4 FFMA2
// (LDS instructions halved, FMA floor unchanged at 512 cyc/unfold/SM).
// Cross-half combine through a shared partial buffer (2 barriers/unfold).

#define Bsz 512
#define Ssz 512
#define Dsz 128
#define Hsz 128
#define UNFOLDS 6

__device__ float g_xin[(size_t)Bsz * Ssz * Hsz];   // [b][s][h] scratch

__device__ __forceinline__ unsigned long long ffma2(unsigned long long a,
                                                    unsigned long long b,
                                                    unsigned long long c) {
    unsigned long long d;
    asm("fma.rn.f32x2 %0, %1, %2, %3;" : "=l"(d) : "l"(a), "l"(b), "l"(c));
    return d;
}

__device__ __forceinline__ float f2sum(unsigned long long v) {
    float lo, hi;
    asm("mov.b64 {%0, %1}, %2;" : "=f"(lo), "=f"(hi) : "l"(v));
    return lo + hi;
}

__device__ __forceinline__ float ftanh(float s) {
    float e = __expf(2.0f * s);
    return 1.0f - __fdividef(2.0f, e + 1.0f);
}

// ---------------------------------------------------------------------------
// Kernel 1: xin[b,s,j] = sum_d x[b,s,d] * W_in[j,d] + b_in[j]
// ---------------------------------------------------------------------------
__global__ void __launch_bounds__(128, 3)
xin_kernel(const float* __restrict__ x,
           const float* __restrict__ W_in,
           const float* __restrict__ b_in)
{
    __shared__ float xs[2][4 * Dsz];

    const int j = threadIdx.x;

    unsigned long long wi[64];
    {
        const ulonglong2* wp = (const ulonglong2*)(W_in + j * Dsz);
        #pragma unroll
        for (int c = 0; c < 32; ++c) {
            ulonglong2 v = wp[c];
            wi[2 * c]     = v.x;
            wi[2 * c + 1] = v.y;
        }
    }
    const float bi = b_in[j];

    const int m0 = blockIdx.x * 128;

    float xf[4];
    #pragma unroll
    for (int r = 0; r < 4; ++r)
        xf[r] = x[(size_t)(m0 + r) * Dsz + j];

    #pragma unroll 1
    for (int ch = 0; ch < 32; ++ch) {
        float* xb = xs[ch & 1];
        #pragma unroll
        for (int r = 0; r < 4; ++r)
            xb[r * Dsz + j] = xf[r];
        __syncthreads();

        if (ch < 31) {
            #pragma unroll
            for (int r = 0; r < 4; ++r)
                xf[r] = x[(size_t)(m0 + (ch + 1) * 4 + r) * Dsz + j];
        }

        unsigned long long a0 = 0ull, a1 = 0ull, a2 = 0ull, a3 = 0ull;
        unsigned long long a4 = 0ull, a5 = 0ull, a6 = 0ull, a7 = 0ull;
        #pragma unroll
        for (int c = 0; c < 32; ++c) {
            ulonglong2 v0 = *(const ulonglong2*)(xb + 0 * Dsz + 4 * c);
            ulonglong2 v1 = *(const ulonglong2*)(xb + 1 * Dsz + 4 * c);
            ulonglong2 v2 = *(const ulonglong2*)(xb + 2 * Dsz + 4 * c);
            ulonglong2 v3 = *(const ulonglong2*)(xb + 3 * Dsz + 4 * c);
            a0 = ffma2(wi[2 * c], v0.x, a0);  a1 = ffma2(wi[2 * c + 1], v0.y, a1);
            a2 = ffma2(wi[2 * c], v1.x, a2);  a3 = ffma2(wi[2 * c + 1], v1.y, a3);
            a4 = ffma2(wi[2 * c], v2.x, a4);  a5 = ffma2(wi[2 * c + 1], v2.y, a5);
            a6 = ffma2(wi[2 * c], v3.x, a6);  a7 = ffma2(wi[2 * c + 1], v3.y, a7);
        }
        const int m = m0 + ch * 4;
        g_xin[(size_t)(m + 0) * Hsz + j] = f2sum(a0) + f2sum(a1) + bi;
        g_xin[(size_t)(m + 1) * Hsz + j] = f2sum(a2) + f2sum(a3) + bi;
        g_xin[(size_t)(m + 2) * Hsz + j] = f2sum(a4) + f2sum(a5) + bi;
        g_xin[(size_t)(m + 3) * Hsz + j] = f2sum(a6) + f2sum(a7) + bi;
    }
}

// ---------------------------------------------------------------------------
// Kernel 2: sequential scan. grid 128 x 256 threads, 4 rows/CTA.
// Thread (p, hf, rp): units j0=2p, j1=2p+1; k in [64*hf, 64*hf+64);
// rows 2*rp, 2*rp+1. Owner identity for h-state: (jown = tid&127, row-pair rp).
// ---------------------------------------------------------------------------
__global__ void __launch_bounds__(256, 1)
ltc_main(const float* __restrict__ W_r,
         const float* __restrict__ b_r,
         const float* __restrict__ W_fc,
         const float* __restrict__ b_fc,
         float* __restrict__ out)
{
    __shared__ float hs[4][Hsz];           // published hidden state
    __shared__ float part[2][4][Hsz];      // [k-half][row][j] partial dots
    __shared__ float red[4][Hsz];          // final reduction scratch

    const int tid  = threadIdx.x;
    const int p    = tid & 63;             // j-pair index
    const int hf   = (tid >> 6) & 1;       // k-half
    const int rp   = tid >> 7;             // row-pair
    const int k0   = hf << 6;
    const int j0   = 2 * p;
    const int jown = tid & 127;            // owned hidden unit
    const int r0   = 2 * rp, r1 = 2 * rp + 1;
    const int base = blockIdx.x * 4;

    // W_r rows j0, j0+1, columns [k0, k0+64): 128 floats in registers.
    unsigned long long wA[32], wB[32];
    {
        const ulonglong2* wpA = (const ulonglong2*)(W_r + (size_t)j0 * Hsz + k0);
        const ulonglong2* wpB = (const ulonglong2*)(W_r + (size_t)(j0 + 1) * Hsz + k0);
        #pragma unroll
        for (int c = 0; c < 16; ++c) {
            ulonglong2 vA = wpA[c];
            ulonglong2 vB = wpB[c];
            wA[2 * c] = vA.x;  wA[2 * c + 1] = vA.y;
            wB[2 * c] = vB.x;  wB[2 * c + 1] = vB.y;
        }
    }

    const float bb  = b_r[jown];
    const float wfc = W_fc[jown];

    float h0 = 0.f, h1 = 0.f;   // owned: (jown, r0) and (jown, r1)

    const size_t xi0 = (size_t)(base + r0) * Ssz * Hsz + jown;
    const size_t xi1 = (size_t)(base + r1) * Ssz * Hsz + jown;
    float xf0 = g_xin[xi0], xf1 = g_xin[xi1];

    #pragma unroll 1
    for (int t = 0; t < Ssz; ++t) {
        const float xin0 = xf0 + bb, xin1 = xf1 + bb;
        if (t + 1 < Ssz) {
            const size_t o = (size_t)(t + 1) * Hsz;
            xf0 = g_xin[xi0 + o];
            xf1 = g_xin[xi1 + o];
        }

        #pragma unroll 1
        for (int u = 0; u < UNFOLDS; ++u) {
            // 1) publish owned h
            hs[r0][jown] = h0;
            hs[r1][jown] = h1;
            __syncthreads();

            // 2) partial dots: 2 units x 2 rows over this thread's k-half.
            //    Each 16B broadcast h-load feeds 4 FFMA2.
            unsigned long long a00 = 0ull, a01 = 0ull, a10 = 0ull, a11 = 0ull;
            unsigned long long b00 = 0ull, b01 = 0ull, b10 = 0ull, b11 = 0ull;
            #pragma unroll          // full unroll: wA/wB must stay in registers
            for (int c = 0; c < 16; ++c) {
                ulonglong2 v0 = *(const ulonglong2*)&hs[r0][k0 + 4 * c];
                ulonglong2 v1 = *(const ulonglong2*)&hs[r1][k0 + 4 * c];
                a00 = ffma2(wA[2 * c], v0.x, a00);  a01 = ffma2(wA[2 * c + 1], v0.y, a01);
                a10 = ffma2(wB[2 * c], v0.x, a10);  a11 = ffma2(wB[2 * c + 1], v0.y, a11);
                b00 = ffma2(wA[2 * c], v1.x, b00);  b01 = ffma2(wA[2 * c + 1], v1.y, b01);
                b10 = ffma2(wB[2 * c], v1.x, b10);  b11 = ffma2(wB[2 * c + 1], v1.y, b11);
            }
            float2 pr0, pr1;
            pr0.x = f2sum(a00) + f2sum(a01);   // (j0,   r0)
            pr0.y = f2sum(a10) + f2sum(a11);   // (j0+1, r0)
            pr1.x = f2sum(b00) + f2sum(b01);   // (j0,   r1)
            pr1.y = f2sum(b10) + f2sum(b11);   // (j0+1, r1)
            *(float2*)&part[hf][r0][j0] = pr0;
            *(float2*)&part[hf][r1][j0] = pr1;
            __syncthreads();

            // 3) combine halves + nonlinearity on owned states
            const float s0 = part[0][r0][jown] + part[1][r0][jown] + xin0;
            const float s1 = part[0][r1][jown] + part[1][r1][jown] + xin1;
            h0 = 0.9f * h0 + 0.1f * ftanh(s0);
            h1 = 0.9f * h1 + 0.1f * ftanh(s1);
        }
    }

    // out[b] = b_fc + sum_j h[b][j] * W_fc[j]
    __syncthreads();
    red[r0][jown] = h0 * wfc;
    red[r1][jown] = h1 * wfc;
    __syncthreads();

    const int wid = tid >> 5, lane = tid & 31;
    if (wid < 4) {
        float4 v = *(const float4*)&red[wid][4 * lane];
        float s = (v.x + v.y) + (v.z + v.w);
        #pragma unroll
        for (int d = 16; d > 0; d >>= 1)
            s += __shfl_xor_sync(0xffffffffu, s, d);
        if (lane == 0)
            out[base + wid] = s + b_fc[0];
    }
}

extern "C" void kernel_launch(void* const* d_in, const int* in_sizes, int n_in,
                              void* d_out, int out_size)
{
    const float* x    = (const float*)d_in[0];
    const float* W_in = (const float*)d_in[1];
    const float* b_in = (const float*)d_in[2];
    const float* W_r  = (const float*)d_in[3];
    const float* b_r  = (const float*)d_in[4];
    const float* W_fc = (const float*)d_in[5];
    const float* b_fc = (const float*)d_in[6];
    float* out = (float*)d_out;

    xin_kernel<<<(Bsz * Ssz) / 128, 128>>>(x, W_in, b_in);
    ltc_main<<<Bsz / 4, 256>>>(W_r, b_r, W_fc, b_fc, out);
}